// round 3
// baseline (speedup 1.0000x reference)
#include <cuda_runtime.h>
#include <cstdint>

#define H 128
#define MAXN 102400
#define BM 128
#define KC 32

// Scratch (device-global arrays are the sanctioned allocation-free scratch).
__device__ float g_agg[(size_t)MAXN * H];
__device__ float g_h1[(size_t)MAXN * H];

__device__ __forceinline__ unsigned f2tf32(float x) {
    unsigned r;
    asm volatile("cvt.rna.tf32.f32 %0, %1;" : "=r"(r) : "f"(x));
    return r;
}

__device__ __forceinline__ void mma_tf32(float c[4], const unsigned a[4], const unsigned b[2]) {
    asm volatile(
        "mma.sync.aligned.m16n8k8.row.col.f32.tf32.tf32.f32 "
        "{%0,%1,%2,%3}, {%4,%5,%6,%7}, {%8,%9}, {%0,%1,%2,%3};"
        : "+f"(c[0]), "+f"(c[1]), "+f"(c[2]), "+f"(c[3])
        : "r"(a[0]), "r"(a[1]), "r"(a[2]), "r"(a[3]), "r"(b[0]), "r"(b[1]));
}

// One warp per edge: 32 lanes x float4 = 128 features. 4 scalar REDs per lane.
// edge_index is int32 (JAX demotes int64 without x64 mode).
__global__ void scatter_kernel(const float* __restrict__ ea,
                               const int* __restrict__ ei,
                               float* __restrict__ agg, int E) {
    long long idx = (long long)blockIdx.x * blockDim.x + threadIdx.x;
    int e = (int)(idx >> 5);
    if (e >= E) return;
    int c = ((int)idx & 31) << 2;
    int col = ei[E + e];  // edge_index[1][e]
    const float4 v = *reinterpret_cast<const float4*>(ea + (long long)e * H + c);
    float* dst = agg + (long long)col * H + c;
    atomicAdd(dst + 0, v.x);
    atomicAdd(dst + 1, v.y);
    atomicAdd(dst + 2, v.z);
    atomicAdd(dst + 3, v.w);
}

// Fused GEMM (tf32 mma.sync) + bias + LayerNorm + shifted softplus.
// out[n, j] = ssp(LN(in @ W + b)).  Block: 128 rows x 128 cols, 8 warps (4M x 2N).
template <int K, bool CONCAT>
__global__ __launch_bounds__(256) void layer_kernel(
    const float* __restrict__ in0,    // [N, H]
    const float* __restrict__ in1,    // [N, H] (agg half of concat) or nullptr
    const float* __restrict__ W,      // [K, H] row-major
    const float* __restrict__ bias,   // [H]
    const float* __restrict__ gamma,  // [H]
    const float* __restrict__ beta,   // [H]
    float* __restrict__ out,          // [N, H]
    int N) {
    __shared__ unsigned As[KC * BM];  // fragment-ordered A tile
    __shared__ unsigned Bs[KC * H];   // fragment-ordered B tile
    __shared__ float sbias[H], sg[H], sbe[H];
    __shared__ float2 sred[BM][2];

    const int tid = threadIdx.x;
    const int lane = tid & 31;
    const int warp = tid >> 5;
    const int wm = warp >> 1;  // 0..3 (M)
    const int wn = warp & 1;   // 0..1 (N)
    const int m0 = blockIdx.x * BM;

    if (tid < H) {
        sbias[tid] = bias[tid];
        sg[tid] = gamma[tid];
        sbe[tid] = beta[tid];
    }

    float acc[2][8][4];
#pragma unroll
    for (int a = 0; a < 2; a++)
#pragma unroll
        for (int b = 0; b < 8; b++)
#pragma unroll
            for (int c = 0; c < 4; c++) acc[a][b][c] = 0.f;

    for (int k0 = 0; k0 < K; k0 += KC) {
        __syncthreads();  // protect smem tiles from previous iteration's reads
        // ---- load A tile (128 rows x KC), scatter into mma-fragment order ----
#pragma unroll
        for (int it = 0; it < 4; ++it) {
            int idx = it * 256 + tid;   // 0..1023 float4 slots
            int m = idx >> 3;           // 0..127 row
            int kq = (idx & 7) << 2;    // 0..28 step 4
            int row = m0 + m;
            float4 v = make_float4(0.f, 0.f, 0.f, 0.f);
            if (row < N) {
                int kg = k0 + kq;
                const float* src;
                if (CONCAT && kg >= H) src = in1 + (long long)row * H + (kg - H);
                else                   src = in0 + (long long)row * H + kg;
                v = *reinterpret_cast<const float4*>(src);
            }
            int t = m >> 4, r = m & 15;
            float vv[4] = {v.x, v.y, v.z, v.w};
#pragma unroll
            for (int j = 0; j < 4; ++j) {
                int kk = kq + j;
                int s = kk >> 3, k8 = kk & 7;
                int ln = ((r & 7) << 2) | (k8 & 3);
                int slot = (r >> 3) | ((k8 >> 2) << 1);
                As[((((s << 3) | t) << 5) | ln) * 4 + slot] = f2tf32(vv[j]);
            }
        }
        // ---- load B tile (KC x 128) from W, scatter into fragment order ----
#pragma unroll
        for (int it = 0; it < 4; ++it) {
            int idx = it * 256 + tid;
            int kk = idx >> 5;          // 0..31
            int nq = (idx & 31) << 2;   // 0..124
            const float4 v = *reinterpret_cast<const float4*>(W + (long long)(k0 + kk) * H + nq);
            int s = kk >> 3, k8 = kk & 7;
            int slot = k8 >> 2;
            float vv[4] = {v.x, v.y, v.z, v.w};
#pragma unroll
            for (int j = 0; j < 4; ++j) {
                int n = nq + j;
                int u = n >> 3;
                int ln = ((n & 7) << 2) | (k8 & 3);
                Bs[((((s << 4) | u) << 5) | ln) * 2 + slot] = f2tf32(vv[j]);
            }
        }
        __syncthreads();
        // ---- compute ----
        const uint4* As4 = reinterpret_cast<const uint4*>(As);
        const uint2* Bs2 = reinterpret_cast<const uint2*>(Bs);
#pragma unroll
        for (int s = 0; s < KC / 8; ++s) {
            uint4 afr[2];
#pragma unroll
            for (int t2 = 0; t2 < 2; ++t2)
                afr[t2] = As4[(((s << 3) | (wm * 2 + t2)) << 5) + lane];
            uint2 bfr[8];
#pragma unroll
            for (int u = 0; u < 8; ++u)
                bfr[u] = Bs2[((((s << 4) | (wn * 8 + u)) << 5)) + lane];
#pragma unroll
            for (int t2 = 0; t2 < 2; ++t2) {
                unsigned a[4] = {afr[t2].x, afr[t2].y, afr[t2].z, afr[t2].w};
#pragma unroll
                for (int u = 0; u < 8; ++u) {
                    unsigned b[2] = {bfr[u].x, bfr[u].y};
                    mma_tf32(acc[t2][u], a, b);
                }
            }
        }
    }

    // ---- epilogue: bias + LayerNorm + shifted softplus ----
    const int g = lane >> 2, tq = lane & 3;
    float s1[2][2] = {{0.f, 0.f}, {0.f, 0.f}};
    float s2[2][2] = {{0.f, 0.f}, {0.f, 0.f}};
#pragma unroll
    for (int t2 = 0; t2 < 2; ++t2)
#pragma unroll
        for (int u = 0; u < 8; ++u) {
            int colb = wn * 64 + u * 8 + tq * 2;
            acc[t2][u][0] += sbias[colb];
            acc[t2][u][1] += sbias[colb + 1];
            acc[t2][u][2] += sbias[colb];
            acc[t2][u][3] += sbias[colb + 1];
            s1[t2][0] += acc[t2][u][0] + acc[t2][u][1];
            s2[t2][0] += acc[t2][u][0] * acc[t2][u][0] + acc[t2][u][1] * acc[t2][u][1];
            s1[t2][1] += acc[t2][u][2] + acc[t2][u][3];
            s2[t2][1] += acc[t2][u][2] * acc[t2][u][2] + acc[t2][u][3] * acc[t2][u][3];
        }
#pragma unroll
    for (int off = 1; off <= 2; off <<= 1) {
#pragma unroll
        for (int t2 = 0; t2 < 2; ++t2)
#pragma unroll
            for (int hh = 0; hh < 2; ++hh) {
                s1[t2][hh] += __shfl_xor_sync(0xffffffffu, s1[t2][hh], off);
                s2[t2][hh] += __shfl_xor_sync(0xffffffffu, s2[t2][hh], off);
            }
    }
    if (tq == 0) {
#pragma unroll
        for (int t2 = 0; t2 < 2; ++t2)
#pragma unroll
            for (int hh = 0; hh < 2; ++hh) {
                int rowl = wm * 32 + t2 * 16 + hh * 8 + g;
                sred[rowl][wn] = make_float2(s1[t2][hh], s2[t2][hh]);
            }
    }
    __syncthreads();
#pragma unroll
    for (int t2 = 0; t2 < 2; ++t2)
#pragma unroll
        for (int hh = 0; hh < 2; ++hh) {
            int rowl = wm * 32 + t2 * 16 + hh * 8 + g;
            float2 r0 = sred[rowl][0], r1 = sred[rowl][1];
            float S1 = r0.x + r1.x, S2 = r0.y + r1.y;
            float mu = S1 * (1.f / H);
            float var = S2 * (1.f / H) - mu * mu;
            float rs = rsqrtf(var + 1e-5f);
            int row = m0 + rowl;
            if (row < N) {
#pragma unroll
                for (int u = 0; u < 8; ++u) {
                    int colb = wn * 64 + u * 8 + tq * 2;
                    float y0 = (acc[t2][u][hh * 2 + 0] - mu) * rs * sg[colb] + sbe[colb];
                    float y1 = (acc[t2][u][hh * 2 + 1] - mu) * rs * sg[colb + 1] + sbe[colb + 1];
                    float2 o;
                    o.x = fmaxf(y0, 0.f) + log1pf(__expf(-fabsf(y0))) - 0.69314718055994531f;
                    o.y = fmaxf(y1, 0.f) + log1pf(__expf(-fabsf(y1))) - 0.69314718055994531f;
                    *reinterpret_cast<float2*>(out + (long long)row * H + colb) = o;
                }
            }
        }
}

extern "C" void kernel_launch(void* const* d_in, const int* in_sizes, int n_in,
                              void* d_out, int out_size) {
    const float* x        = (const float*)d_in[0];
    const int* ei         = (const int*)d_in[1];
    const float* ea       = (const float*)d_in[2];
    const float* W1       = (const float*)d_in[3];
    const float* b1       = (const float*)d_in[4];
    const float* g1       = (const float*)d_in[5];
    const float* be1      = (const float*)d_in[6];
    const float* W2       = (const float*)d_in[7];
    const float* b2       = (const float*)d_in[8];
    const float* g2       = (const float*)d_in[9];
    const float* be2      = (const float*)d_in[10];
    const float* W3       = (const float*)d_in[11];
    const float* b3       = (const float*)d_in[12];
    const float* g3       = (const float*)d_in[13];
    const float* be3      = (const float*)d_in[14];
    float* out = (float*)d_out;

    int N = in_sizes[0] / H;
    int E = in_sizes[1] / 2;

    float *agg, *h1;
    cudaGetSymbolAddress((void**)&agg, g_agg);
    cudaGetSymbolAddress((void**)&h1, g_h1);

    cudaMemsetAsync(agg, 0, (size_t)N * H * sizeof(float));

    {
        long long tot = (long long)E * 32;
        int blocks = (int)((tot + 255) / 256);
        scatter_kernel<<<blocks, 256>>>(ea, ei, agg, E);
    }

    int gb = (N + BM - 1) / BM;
    layer_kernel<2 * H, true><<<gb, 256>>>(x, agg, W1, b1, g1, be1, h1, N);
    layer_kernel<H, false><<<gb, 256>>>(h1, nullptr, W2, b2, g2, be2, agg, N);
    layer_kernel<H, false><<<gb, 256>>>(agg, nullptr, W3, b3, g3, be3, out, N);
}

// round 5
// speedup vs baseline: 2.1597x; 2.1597x over previous
#include <cuda_runtime.h>
#include <cstdint>

#define H 128
#define MAXN 102400

// ---------------- scratch (device globals = sanctioned scratch) ----------------
__device__ float g_agg[(size_t)MAXN * H];
__device__ float g_h1[(size_t)MAXN * H];
__device__ uint4 g_wf1[32 * 8 * 32];  // K=256: s=32, u2=8, lane=32  (128KB)
__device__ uint4 g_wf2[16 * 8 * 32];  // K=128
__device__ uint4 g_wf3[16 * 8 * 32];

__device__ __forceinline__ unsigned f2tf32(float x) {
    unsigned r;
    asm volatile("cvt.rna.tf32.f32 %0, %1;" : "=r"(r) : "f"(x));
    return r;
}

__device__ __forceinline__ void mma_tf32(float c[4], const unsigned a[4], const unsigned b[2]) {
    asm volatile(
        "mma.sync.aligned.m16n8k8.row.col.f32.tf32.tf32.f32 "
        "{%0,%1,%2,%3}, {%4,%5,%6,%7}, {%8,%9}, {%0,%1,%2,%3};"
        : "+f"(c[0]), "+f"(c[1]), "+f"(c[2]), "+f"(c[3])
        : "r"(a[0]), "r"(a[1]), "r"(a[2]), "r"(a[3]), "r"(b[0]), "r"(b[1]));
}

// ---------------- weight pre-pack: W [K,128] row-major -> B fragments ----------------
// Wf[(s*8+u2)*32 + lane] = uint4{ b0(u=2*u2), b1(u=2*u2), b0(u=2*u2+1), b1(u=2*u2+1) }
// B frag (col-major, m16n8k8): lane l: b0 = B[k=l&3][n=l>>2], b1 = B[k=(l&3)+4][n=l>>2]
__global__ void wpack_kernel(const float* __restrict__ W, uint4* __restrict__ Wf, int K) {
    int idx = blockIdx.x * blockDim.x + threadIdx.x;
    int total = (K / 8) * 8 * 32;
    if (idx >= total) return;
    int lane = idx & 31;
    int u2 = (idx >> 5) & 7;
    int s = idx >> 8;
    int n_e = u2 * 16 + (lane >> 2);
    int n_o = n_e + 8;
    int k = s * 8 + (lane & 3);
    uint4 v;
    v.x = f2tf32(W[(long long)k * H + n_e]);
    v.y = f2tf32(W[(long long)(k + 4) * H + n_e]);
    v.z = f2tf32(W[(long long)k * H + n_o]);
    v.w = f2tf32(W[(long long)(k + 4) * H + n_o]);
    Wf[idx] = v;
}

// ---------------- scatter: one warp per edge, red.v4 per lane ----------------
__global__ void scatter_kernel(const float* __restrict__ ea,
                               const int* __restrict__ ei,
                               float* __restrict__ agg, int E) {
    long long idx = (long long)blockIdx.x * blockDim.x + threadIdx.x;
    int e = (int)(idx >> 5);
    if (e >= E) return;
    int c = ((int)idx & 31) << 2;
    int col = ei[E + e];  // edge_index[1][e] (int32)
    const float4 v = *reinterpret_cast<const float4*>(ea + (long long)e * H + c);
    float* dst = agg + (long long)col * H + c;
    asm volatile("red.global.add.v4.f32 [%0], {%1, %2, %3, %4};"
                 :: "l"(dst), "f"(v.x), "f"(v.y), "f"(v.z), "f"(v.w) : "memory");
}

// ---------------- fused layer: smem-free mma.sync GEMM + bias + LN + ssp ----------------
// 256 threads = 8 warps; warp owns 16 rows x all 128 cols. No shared memory, no syncs.
template <int S, bool CONCAT>
__global__ __launch_bounds__(256, 2) void layer_mma(
    const float* __restrict__ a0src,   // rows source, k in [0,128)
    const float* __restrict__ a1src,   // rows source, k in [128,256) (CONCAT) or nullptr
    const uint4* __restrict__ Wf,      // fragment-packed weights
    const float* __restrict__ bias, const float* __restrict__ gamma,
    const float* __restrict__ beta, float* __restrict__ out, int N) {
    const int tid = threadIdx.x;
    const int w = tid >> 5;
    const int lane = tid & 31;
    const int t4 = lane & 3;
    const int m0 = blockIdx.x * 128 + w * 16;
    const int r0 = m0 + (lane >> 2);
    const int r1 = r0 + 8;
    const long long r0c = (long long)min(r0, N - 1) * H;
    const long long r1c = (long long)min(r1, N - 1) * H;

    float acc[16][4];
#pragma unroll
    for (int u = 0; u < 16; ++u)
#pragma unroll
        for (int j = 0; j < 4; ++j) acc[u][j] = 0.f;

#pragma unroll
    for (int s = 0; s < S; ++s) {
        const float* src;
        int kb;
        if (CONCAT && s >= 16) { src = a1src; kb = s * 8 - 128; }
        else                   { src = a0src; kb = s * 8; }
        unsigned a[4];
        a[0] = f2tf32(__ldg(src + r0c + kb + t4));
        a[1] = f2tf32(__ldg(src + r1c + kb + t4));
        a[2] = f2tf32(__ldg(src + r0c + kb + t4 + 4));
        a[3] = f2tf32(__ldg(src + r1c + kb + t4 + 4));
        const uint4* wf = Wf + (s * 8) * 32 + lane;
#pragma unroll
        for (int u2 = 0; u2 < 8; ++u2) {
            const uint4 bb = __ldg(wf + u2 * 32);
            unsigned b0[2] = {bb.x, bb.y};
            unsigned b1[2] = {bb.z, bb.w};
            mma_tf32(acc[u2 * 2], a, b0);
            mma_tf32(acc[u2 * 2 + 1], a, b1);
        }
    }

    // ---- epilogue: bias + per-row LN (quad shuffle) + shifted softplus ----
    float s1a = 0.f, s2a = 0.f, s1b = 0.f, s2b = 0.f;
#pragma unroll
    for (int u = 0; u < 16; ++u) {
        int cb = u * 8 + t4 * 2;
        const float2 b2 = *reinterpret_cast<const float2*>(bias + cb);
        acc[u][0] += b2.x; acc[u][1] += b2.y;
        acc[u][2] += b2.x; acc[u][3] += b2.y;
        s1a += acc[u][0] + acc[u][1];
        s2a += acc[u][0] * acc[u][0] + acc[u][1] * acc[u][1];
        s1b += acc[u][2] + acc[u][3];
        s2b += acc[u][2] * acc[u][2] + acc[u][3] * acc[u][3];
    }
#pragma unroll
    for (int off = 1; off <= 2; off <<= 1) {
        s1a += __shfl_xor_sync(0xffffffffu, s1a, off);
        s2a += __shfl_xor_sync(0xffffffffu, s2a, off);
        s1b += __shfl_xor_sync(0xffffffffu, s1b, off);
        s2b += __shfl_xor_sync(0xffffffffu, s2b, off);
    }
    const float inv = 1.f / (float)H;
    float mu0 = s1a * inv, rs0 = rsqrtf(s2a * inv - mu0 * mu0 + 1e-5f);
    float mu1 = s1b * inv, rs1 = rsqrtf(s2b * inv - mu1 * mu1 + 1e-5f);
    const float LN2 = 0.69314718055994531f;

    if (r0 < N) {
        float* op = out + (long long)r0 * H;
#pragma unroll
        for (int u = 0; u < 16; ++u) {
            int cb = u * 8 + t4 * 2;
            const float2 gg = *reinterpret_cast<const float2*>(gamma + cb);
            const float2 be = *reinterpret_cast<const float2*>(beta + cb);
            float y0 = (acc[u][0] - mu0) * rs0 * gg.x + be.x;
            float y1 = (acc[u][1] - mu0) * rs0 * gg.y + be.y;
            float2 o;
            o.x = fmaxf(y0, 0.f) + log1pf(__expf(-fabsf(y0))) - LN2;
            o.y = fmaxf(y1, 0.f) + log1pf(__expf(-fabsf(y1))) - LN2;
            *reinterpret_cast<float2*>(op + cb) = o;
        }
    }
    if (r1 < N) {
        float* op = out + (long long)r1 * H;
#pragma unroll
        for (int u = 0; u < 16; ++u) {
            int cb = u * 8 + t4 * 2;
            const float2 gg = *reinterpret_cast<const float2*>(gamma + cb);
            const float2 be = *reinterpret_cast<const float2*>(beta + cb);
            float y0 = (acc[u][2] - mu1) * rs1 * gg.x + be.x;
            float y1 = (acc[u][3] - mu1) * rs1 * gg.y + be.y;
            float2 o;
            o.x = fmaxf(y0, 0.f) + log1pf(__expf(-fabsf(y0))) - LN2;
            o.y = fmaxf(y1, 0.f) + log1pf(__expf(-fabsf(y1))) - LN2;
            *reinterpret_cast<float2*>(op + cb) = o;
        }
    }
}

// ---------------- launch ----------------
extern "C" void kernel_launch(void* const* d_in, const int* in_sizes, int n_in,
                              void* d_out, int out_size) {
    const float* x   = (const float*)d_in[0];
    const int* ei    = (const int*)d_in[1];
    const float* ea  = (const float*)d_in[2];
    const float* W1  = (const float*)d_in[3];
    const float* b1  = (const float*)d_in[4];
    const float* g1  = (const float*)d_in[5];
    const float* be1 = (const float*)d_in[6];
    const float* W2  = (const float*)d_in[7];
    const float* b2  = (const float*)d_in[8];
    const float* g2  = (const float*)d_in[9];
    const float* be2 = (const float*)d_in[10];
    const float* W3  = (const float*)d_in[11];
    const float* b3  = (const float*)d_in[12];
    const float* g3  = (const float*)d_in[13];
    const float* be3 = (const float*)d_in[14];
    float* out = (float*)d_out;

    int N = in_sizes[0] / H;
    int E = in_sizes[1] / 2;

    float *agg, *h1;
    uint4 *wf1, *wf2, *wf3;
    cudaGetSymbolAddress((void**)&agg, g_agg);
    cudaGetSymbolAddress((void**)&h1, g_h1);
    cudaGetSymbolAddress((void**)&wf1, g_wf1);
    cudaGetSymbolAddress((void**)&wf2, g_wf2);
    cudaGetSymbolAddress((void**)&wf3, g_wf3);

    cudaMemsetAsync(agg, 0, (size_t)N * H * sizeof(float));

    // weight fragment packing (tiny)
    wpack_kernel<<<32, 256>>>(W1, wf1, 256);
    wpack_kernel<<<16, 256>>>(W2, wf2, 128);
    wpack_kernel<<<16, 256>>>(W3, wf3, 128);

    // scatter
    {
        long long tot = (long long)E * 32;
        int blocks = (int)((tot + 255) / 256);
        scatter_kernel<<<blocks, 256>>>(ea, ei, agg, E);
    }

    int gb = (N + 127) / 128;
    layer_mma<32, true><<<gb, 256>>>(x, agg, wf1, b1, g1, be1, h1, N);
    layer_mma<16, false><<<gb, 256>>>(h1, nullptr, wf2, b2, g2, be2, agg, N);
    layer_mma<16, false><<<gb, 256>>>(agg, nullptr, wf3, b3, g3, be3, out, N);
}